// round 7
// baseline (speedup 1.0000x reference)
#include <cuda_runtime.h>
#include <math.h>
#include <stdint.h>

// ---------------- problem constants (fixed shapes) ----------------
#define BB    64      // batch
#define HH    512     // hidden
#define DD    512     // input dim
#define NBLK  128     // persistent blocks; block i owns hidden dims [4i,4i+4)
#define NTHR  512
#define KTOT  1024    // GEMM K = D + H
#define WST   1032    // SMEM weight row stride (1024 + 8 pad)
#define NKSL  8       // k-slices (each 128 k)
#define ATTN_THRESH 1e-10f

// ---------------- SMEM layout (float offsets) ----------------
#define OFF_W     0
#define SZ_W      (16*WST)              // 16512
#define OFF_RED   (OFF_W + SZ_W)
#define SZ_RED    (NKSL*1088)           // 8704 (64 tiles * 17 stride)
#define OFF_ATTNA (OFF_RED + SZ_RED)
#define OFF_ATTNB (OFF_ATTNA + 1024)
#define OFF_GATES (OFF_ATTNB + 1024)    // 16 rows x 64 b
#define OFF_C     (OFF_GATES + 1024)    // 256
#define OFF_H2    (OFF_C + 256)         // 256
#define OFF_BS    (OFF_H2 + 256)        // 16
#define OFF_WSP   (OFF_BS + 16)         // 8
#define OFF_BSP   (OFF_WSP + 8)         // 2
#define OFF_SCR   (OFF_BSP + 2)         // 32 reduce scratch
#define OFF_WIN   (OFF_SCR + 32)        // 2 ints
#define SMEM_FLOATS (OFF_WIN + 4)
#define SMEM_BYTES  (SMEM_FLOATS*4)

// ---------------- persistent global state (no allocs allowed) ----------------
// g_AT2: k-pair interleaved activations: element (k,b) at (k>>1)*128 + b*2 + (k&1)
// k < 512 -> time_in rows, k >= 512 -> h rows.
__device__ __align__(16) float g_AT2[KTOT * BB];
__device__ float    g_spp[BB * 256];     // sp partials, batch-major: [b][g][blk]
__device__ unsigned g_cnt;
__device__ unsigned g_gen;

// ---------------- f32x2 packed-FMA helpers ----------------
__device__ __forceinline__ void fma2(unsigned long long &d,
                                     unsigned long long a, unsigned long long b) {
    asm("fma.rn.f32x2 %0, %1, %2, %0;" : "+l"(d) : "l"(a), "l"(b));
}
__device__ __forceinline__ void split2(float4 w, unsigned long long &lo,
                                       unsigned long long &hi) {
    asm("mov.b64 %0, {%2, %3};\n\tmov.b64 %1, {%4, %5};"
        : "=l"(lo), "=l"(hi) : "f"(w.x), "f"(w.y), "f"(w.z), "f"(w.w));
}
__device__ __forceinline__ float hsum2(unsigned long long v) {
    float lo, hi;
    asm("mov.b64 {%0, %1}, %2;" : "=f"(lo), "=f"(hi) : "l"(v));
    return lo + hi;
}

// ---------------- grid-wide barrier (all 128 blocks co-resident) ----------------
__device__ __forceinline__ void grid_barrier() {
    __syncthreads();
    __threadfence();
    if (threadIdx.x == 0) {
        unsigned gen = *(volatile unsigned*)&g_gen;
        if (atomicAdd(&g_cnt, 1u) == gridDim.x - 1) {
            atomicExch(&g_cnt, 0u);
            __threadfence();
            atomicExch(&g_gen, gen + 1u);
        } else {
            while (*(volatile unsigned*)&g_gen == gen) { __nanosleep(32); }
        }
    }
    __syncthreads();
    __threadfence();   // acquire + L1D invalidate for cross-SM g_AT2 reads
}

// ---------------- block reductions over 512 threads (16 warps) ----------------
__device__ __forceinline__ float brsum(float v, float* scr) {
#pragma unroll
    for (int o = 16; o; o >>= 1) v += __shfl_xor_sync(0xffffffffu, v, o);
    __syncthreads();
    if ((threadIdx.x & 31) == 0) scr[threadIdx.x >> 5] = v;
    __syncthreads();
    if (threadIdx.x < 32) {
        float w = (threadIdx.x < 16) ? scr[threadIdx.x] : 0.f;
#pragma unroll
        for (int o = 8; o; o >>= 1) w += __shfl_xor_sync(0xffffffffu, w, o);
        if (threadIdx.x == 0) scr[0] = w;
    }
    __syncthreads();
    return scr[0];
}
__device__ __forceinline__ float brmax(float v, float* scr) {
#pragma unroll
    for (int o = 16; o; o >>= 1) v = fmaxf(v, __shfl_xor_sync(0xffffffffu, v, o));
    __syncthreads();
    if ((threadIdx.x & 31) == 0) scr[threadIdx.x >> 5] = v;
    __syncthreads();
    if (threadIdx.x < 32) {
        float w = (threadIdx.x < 16) ? scr[threadIdx.x] : 0.f;
#pragma unroll
        for (int o = 8; o; o >>= 1) w = fmaxf(w, __shfl_xor_sync(0xffffffffu, w, o));
        if (threadIdx.x == 0) scr[0] = w;
    }
    __syncthreads();
    return scr[0];
}

// ---------------- time_in over attn window; writes g_AT2 tin rows ----------------
__device__ __forceinline__ void compute_tin(const float* __restrict__ input,
                                            const float* __restrict__ an,
                                            float* tinred, int b, int dstart,
                                            int lo, int hi, int tid) {
    __syncthreads();
    const int dloc = tid & 255;
    const int ls   = tid >> 8;       // 0..1
    float s = 0.f;
    const float* xp = input + (size_t)b * 512 + dstart + dloc;
    for (int l = lo + ls; l <= hi; l += 2)
        s = fmaf(xp[(size_t)l * 32768], an[l], s);
    tinred[ls * 256 + dloc] = s;
    __syncthreads();
    if (tid < 256) {
        float v = tinred[tid] + tinred[256 + tid];
        const int k = dstart + tid;
        g_AT2[(k >> 1) * 128 + b * 2 + (k & 1)] = v;
    }
}

// ---------------- persistent kernel ----------------
__global__ void __launch_bounds__(NTHR, 1)
spacing_rnn_kernel(const float* __restrict__ input, const int* __restrict__ plen,
                   const float* __restrict__ Wih, const float* __restrict__ Whh,
                   const float* __restrict__ bih, const float* __restrict__ bhh,
                   const float* __restrict__ Wsp, const float* __restrict__ bsp,
                   float* __restrict__ out, int L)
{
    extern __shared__ float sm[];
    float* Wsm   = sm + OFF_W;
    float* red   = sm + OFF_RED;
    float* attnA = sm + OFF_ATTNA;
    float* attnB = sm + OFF_ATTNB;
    float* gates = sm + OFF_GATES;
    float* csm   = sm + OFF_C;
    float* h2s   = sm + OFF_H2;
    float* bsum  = sm + OFF_BS;
    float* wspc  = sm + OFF_WSP;
    float* bspc  = sm + OFF_BSP;
    float* scr   = sm + OFF_SCR;
    int*   win   = (int*)(sm + OFF_WIN);

    const int tid    = threadIdx.x;
    const int bi     = blockIdx.x;
    const int j0     = bi * 4;
    const int b      = bi & 63;
    const int dstart = (bi >> 6) * 256;
    int len = plen[0];
    if (len <= 0 || len > L) len = L;

    // ---------------- prologue ----------------
    for (int li = tid; li < 16 * 1024; li += NTHR) {
        int r = li >> 10, k = li & 1023;
        int gate = r >> 2, jl = r & 3;
        int grow = gate * 512 + j0 + jl;
        float w = (k < 512) ? Wih[grow * 512 + k] : Whh[grow * 512 + k - 512];
        Wsm[r * WST + k] = w;
    }
    if (tid < 16) {
        int gate = tid >> 2, jl = tid & 3;
        int grow = gate * 512 + j0 + jl;
        bsum[tid] = bih[grow] + bhh[grow];
    }
    if (tid < 8)  wspc[tid] = Wsp[(tid >> 2) * 512 + j0 + (tid & 3)];
    if (tid < 2)  bspc[tid] = bsp[tid];
    attnA[tid] = (tid == 0) ? 1.f : 0.f;
    attnA[tid + 512] = 0.f;
    attnB[tid] = 0.f;
    attnB[tid + 512] = 0.f;
    if (tid < 256) {
        csm[tid] = 0.f;
        const int k = 512 + j0 + (tid & 3);
        g_AT2[(k >> 1) * 128 + (tid >> 2) * 2 + (k & 1)] = 0.f;   // h0 = 0
    }
    __syncthreads();
    compute_tin(input, attnA, red, b, dstart, 0, 0, tid);   // tin(0) = x[:, :, 0]
    grid_barrier();

    float* cur = attnA;
    float* nxt = attnB;
    int sup = 0;

    for (int t = 0; t < len; t++) {
        // ============ PHASE A: gates GEMM (f32x2) + LSTM cell ============
        {
            const int tile = tid & 63;
            const int ks   = tid >> 6;          // 0..7
            const int b0   = (tile & 15) * 4;
            const int r0   = (tile >> 4) * 4;
            const int k0   = ks * 128;
            unsigned long long acc[4][4];
#pragma unroll
            for (int i = 0; i < 4; i++)
#pragma unroll
                for (int j = 0; j < 4; j++) acc[i][j] = 0ull;
            const float* Wb = Wsm + r0 * WST;
#pragma unroll 4
            for (int kk = 0; kk < 128; kk += 4) {
                const int k = k0 + kk;
                float4 w0f = *(const float4*)(Wb + 0 * WST + k);
                float4 w1f = *(const float4*)(Wb + 1 * WST + k);
                float4 w2f = *(const float4*)(Wb + 2 * WST + k);
                float4 w3f = *(const float4*)(Wb + 3 * WST + k);
                const float* pa = g_AT2 + (size_t)(k >> 1) * 128 + b0 * 2;
                ulonglong2 A01 = *(const ulonglong2*)(pa);        // b0,b1 @ (k,k+1)
                ulonglong2 A23 = *(const ulonglong2*)(pa + 4);    // b2,b3 @ (k,k+1)
                ulonglong2 B01 = *(const ulonglong2*)(pa + 128);  // b0,b1 @ (k+2,k+3)
                ulonglong2 B23 = *(const ulonglong2*)(pa + 132);
                unsigned long long wl0, wh0, wl1, wh1, wl2, wh2, wl3, wh3;
                split2(w0f, wl0, wh0); split2(w1f, wl1, wh1);
                split2(w2f, wl2, wh2); split2(w3f, wl3, wh3);
                // k-pair 0
                fma2(acc[0][0], A01.x, wl0); fma2(acc[0][1], A01.x, wl1);
                fma2(acc[0][2], A01.x, wl2); fma2(acc[0][3], A01.x, wl3);
                fma2(acc[1][0], A01.y, wl0); fma2(acc[1][1], A01.y, wl1);
                fma2(acc[1][2], A01.y, wl2); fma2(acc[1][3], A01.y, wl3);
                fma2(acc[2][0], A23.x, wl0); fma2(acc[2][1], A23.x, wl1);
                fma2(acc[2][2], A23.x, wl2); fma2(acc[2][3], A23.x, wl3);
                fma2(acc[3][0], A23.y, wl0); fma2(acc[3][1], A23.y, wl1);
                fma2(acc[3][2], A23.y, wl2); fma2(acc[3][3], A23.y, wl3);
                // k-pair 1
                fma2(acc[0][0], B01.x, wh0); fma2(acc[0][1], B01.x, wh1);
                fma2(acc[0][2], B01.x, wh2); fma2(acc[0][3], B01.x, wh3);
                fma2(acc[1][0], B01.y, wh0); fma2(acc[1][1], B01.y, wh1);
                fma2(acc[1][2], B01.y, wh2); fma2(acc[1][3], B01.y, wh3);
                fma2(acc[2][0], B23.x, wh0); fma2(acc[2][1], B23.x, wh1);
                fma2(acc[2][2], B23.x, wh2); fma2(acc[2][3], B23.x, wh3);
                fma2(acc[3][0], B23.y, wh0); fma2(acc[3][1], B23.y, wh1);
                fma2(acc[3][2], B23.y, wh2); fma2(acc[3][3], B23.y, wh3);
            }
            __syncthreads();
            const int base = ks * 1088 + tile * 17;
#pragma unroll
            for (int i = 0; i < 4; i++)
#pragma unroll
                for (int j = 0; j < 4; j++) red[base + i * 4 + j] = hsum2(acc[i][j]);
        }
        __syncthreads();
        // gather 8 k-slice partials -> gates[r][b] (1024 entries, 2 per thread)
        for (int e = tid; e < 1024; e += NTHR) {
            const int tile = e >> 4, v = e & 15;
            float s = 0.f;
#pragma unroll
            for (int ks2 = 0; ks2 < NKSL; ks2++) s += red[ks2 * 1088 + tile * 17 + v];
            const int bb2 = (tile & 15) * 4 + (v >> 2);
            const int rr  = (tile >> 4) * 4 + (v & 3);
            gates[rr * 64 + bb2] = s;
        }
        __syncthreads();
        if (tid < 256) {  // LSTM cell for (b = tid>>2, jl = tid&3)
            const int bb2 = tid >> 2, jl = tid & 3;
            float gi = gates[(0  + jl) * 64 + bb2] + bsum[0  + jl];
            float gf = gates[(4  + jl) * 64 + bb2] + bsum[4  + jl];
            float gg = gates[(8  + jl) * 64 + bb2] + bsum[8  + jl];
            float go = gates[(12 + jl) * 64 + bb2] + bsum[12 + jl];
            float c  = csm[tid];
            float si = 1.f / (1.f + __expf(-gi));
            float sf = 1.f / (1.f + __expf(-gf));
            float so = 1.f / (1.f + __expf(-go));
            float c2 = sf * c + si * tanhf(gg);
            float h2 = so * tanhf(c2);
            csm[tid] = c2;
            h2s[tid] = h2;
            out[(size_t)t * 32768 + (size_t)bb2 * 512 + j0 + jl] = h2;
        }
        __syncthreads();
        if (tid < 128) {  // sp partial for this block's 4 dims (batch-major store)
            const int g = tid >> 6, bb2 = tid & 63;
            float s = h2s[bb2 * 4 + 0] * wspc[g * 4 + 0] + h2s[bb2 * 4 + 1] * wspc[g * 4 + 1]
                    + h2s[bb2 * 4 + 2] * wspc[g * 4 + 2] + h2s[bb2 * 4 + 3] * wspc[g * 4 + 3];
            g_spp[bb2 * 256 + g * 128 + bi] = s;
        }
        grid_barrier();  // h(t-1) reads done; sp partials visible

        // ============ PHASE B: publish h, attn update, time_in ============
        if (t + 1 < len) {
            if (tid < 256) {  // publish h2 -> g_AT2 (all GEMM reads done)
                const int bb2 = tid >> 2, jl = tid & 3;
                const int k = 512 + j0 + jl;
                g_AT2[(k >> 1) * 128 + bb2 * 2 + (k & 1)] = h2s[tid];
            }
            // --- reduce sp over 128 blocks for batch b (contiguous read) ---
            {
                float v = (tid < 256) ? g_spp[b * 256 + tid] : 0.f;
#pragma unroll
                for (int o = 16; o; o >>= 1) v += __shfl_xor_sync(0xffffffffu, v, o);
                if (tid < 256 && (tid & 31) == 0) scr[16 + (tid >> 5)] = v;  // 8 partials
                __syncthreads();
                if (tid == 0) {
                    float sp0 = scr[16] + scr[17] + scr[18] + scr[19];
                    float sp1 = scr[20] + scr[21] + scr[22] + scr[23];
                    scr[24] = 1.f / (1.f + __expf(-(sp0 + bspc[0])));
                    float pp = sp1 + bspc[1];
                    scr[25] = (pp > 0.f ? pp : 0.f) + 1.f;
                }
                __syncthreads();
            }
            const float shift = scr[24];
            const float p     = scr[25];
            const int sup2 = min(sup + 1, L - 1);
            __syncthreads();
            if (tid == 0) { win[0] = 0x7fffffff; win[1] = -1; }
            // --- attn: shift mix (exact, full support), 2 elems per thread ---
            const int i1 = tid, i2 = tid + 512;
            float a2a = 0.f, a2b = 0.f;
            if (i1 <= sup2) {
                float a  = cur[i1];
                float ap = (i1 > 0) ? cur[i1 - 1] : 0.f;
                a2a = (1.f - shift) * a + shift * ap;
            }
            if (i2 <= sup2) {
                float a  = cur[i2];
                float ap = cur[i2 - 1];
                a2b = (1.f - shift) * a + shift * ap;
            }
            // --- sharpen + normalize (max-scaled pow; identical after normalize) ---
            float amax  = brmax(fmaxf(a2a, a2b), scr);
            float lmax  = __logf(amax);
            float pa2   = (a2a > 0.f) ? __expf(p * (__logf(a2a) - lmax)) : 0.f;
            float pb2   = (a2b > 0.f) ? __expf(p * (__logf(a2b) - lmax)) : 0.f;
            float ssum  = brsum(pa2 + pb2, scr);
            float inv   = 1.f / ssum;
            float na = pa2 * inv, nb = pb2 * inv;
            nxt[i1] = na;
            nxt[i2] = nb;
            if (na >= ATTN_THRESH) { atomicMin(&win[0], i1); atomicMax(&win[1], i1); }
            if (nb >= ATTN_THRESH) { atomicMin(&win[0], i2); atomicMax(&win[1], i2); }
            __syncthreads();
            const int lo = win[0], hi = win[1];
            compute_tin(input, nxt, red, b, dstart, lo, hi, tid);
            float* tsw = cur; cur = nxt; nxt = tsw;
            sup = sup2;
            grid_barrier();  // tin + h published for next phase A
        }
    }
}

extern "C" void kernel_launch(void* const* d_in, const int* in_sizes, int n_in,
                              void* d_out, int out_size) {
    const float* input = (const float*)d_in[0];
    const int*   plen  = (const int*)  d_in[1];
    const float* Wih   = (const float*)d_in[2];
    const float* Whh   = (const float*)d_in[3];
    const float* bih   = (const float*)d_in[4];
    const float* bhh   = (const float*)d_in[5];
    const float* Wsp   = (const float*)d_in[6];
    const float* bsp   = (const float*)d_in[7];
    float* out = (float*)d_out;

    int L = in_sizes[0] / (BB * DD);  // 1000

    cudaFuncSetAttribute(spacing_rnn_kernel,
                         cudaFuncAttributeMaxDynamicSharedMemorySize, SMEM_BYTES);
    spacing_rnn_kernel<<<NBLK, NTHR, SMEM_BYTES>>>(input, plen, Wih, Whh, bih, bhh,
                                                   Wsp, bsp, out, L);
}